// round 5
// baseline (speedup 1.0000x reference)
#include <cuda_runtime.h>

// Problem constants
#define Kc    9
#define NCc   13
#define NAc   5
#define NBc   128
#define NHc   26
#define NWc   26
#define NTc   50
#define Lc    21          // 2K+3
#define NPIX  (NHc*NWc)   // 676
#define NANCH (NAc*NHc*NWc) // 3380
#define CH    (2*Kc+1+NCc) // 32
#define NBMW  106          // ceil(3380/32)

#define THf     80.0f
#define TH2f    6400.0f
#define SILf    0.6f
#define OBJf    5.0f
// 1/(exp(2)-1)
#define INVC0   0.15651764274966574f

#define SXc (640.0f/26.0f)
#define SYc (480.0f/26.0f)

typedef unsigned long long ull;
typedef unsigned int uint;

// Scratch (device globals — no allocation allowed)
// Per (b,t): 20 floats = 5 float4; group g (corner pair 2g,2g+1):
//   [g*4+0]=-gx_{2g}  [g*4+1]=-gx_{2g+1}  [g*4+2]=-gy_{2g}  [g*4+3]=-gy_{2g+1]
// group 4 = (corner 8, pad): pad value 1e18 (never inside)
__device__ __align__(16) float d_gtn[NBc*NTc*20];
__device__ float d_txv[NBc*NTc*Kc];
__device__ float d_tyv[NBc*NTc*Kc];
__device__ float d_conft[NBc*NTc];
__device__ float d_tclsA[NBc*NTc];
__device__ int   d_codeA[NBc*NTc];
__device__ int   d_nvalid[NBc];

__constant__ float c_anch[10] = {1.482f,2.2412f,2.0501f,3.1265f,2.3946f,
                                 4.6891f,3.1018f,3.991f,3.4879f,5.8851f};

__device__ __forceinline__ float sigmoidf_(float x) { return 1.0f/(1.0f+expf(-x)); }

__device__ __forceinline__ ull pack2(float lo, float hi) {
    ull r;
    asm("mov.b64 %0, {%1, %2};" : "=l"(r) : "f"(lo), "f"(hi));
    return r;
}
__device__ __forceinline__ ull fma2_(ull a, ull b, ull c) {
    ull d;
    asm("fma.rn.f32x2 %0, %1, %2, %3;" : "=l"(d) : "l"(a), "l"(b), "l"(c));
    return d;
}
__device__ __forceinline__ ull add2_(ull a, ull b) {
    ull d;
    asm("add.rn.f32x2 %0, %1, %2;" : "=l"(d) : "l"(a), "l"(b));
    return d;
}
__device__ __forceinline__ uint sgn2(ull d) {
    return ((uint)d >> 31) + ((uint)(d >> 32) >> 31);
}
// d^2 - TH^2 for a corner pair (direct form)
__device__ __forceinline__ ull dist2m(ull px, ull py, ull ngx, ull ngy, ull nTH2) {
    ull dx = add2_(px, ngx);
    ull dy = add2_(py, ngy);
    return fma2_(dx, dx, fma2_(dy, dy, nTH2));
}

// One block per batch; thread t handles target t. Also zeroes the loss scalar.
__global__ void region_prep(const float* __restrict__ out,
                            const float* __restrict__ tgt,
                            float* __restrict__ loss)
{
    int b = blockIdx.x;
    int t = threadIdx.x;
    if (b == 0 && t == 0) loss[0] = 0.0f;

    __shared__ int sflag[NTc];
    if (t < NTc)
        sflag[t] = (tgt[(size_t)b*NTc*Lc + (size_t)t*Lc + 1] != 0.0f) ? 1 : 0;
    __syncthreads();
    if (t == 0) {
        int nv = NTc;
        for (int q = 0; q < NTc; ++q) if (!sflag[q]) { nv = q; break; }
        d_nvalid[b] = nv;
    }
    if (t >= NTc) return;

    const float* row = tgt + (size_t)b*NTc*Lc + (size_t)t*Lc;
    float gxr[Kc], gyr[Kc];
#pragma unroll
    for (int k = 0; k < Kc; ++k) { gxr[k] = row[1+2*k]; gyr[k] = row[2+2*k]; }

    int gi0 = (int)floorf(gxr[0]*(float)NWc);
    int gj0 = (int)floorf(gyr[0]*(float)NHc);
    gi0 = min(max(gi0, 0), NWc-1);
    gj0 = min(max(gj0, 0), NHc-1);

    int idx = b*NTc + t;

    float gpx[Kc], gpy[Kc];
#pragma unroll
    for (int k = 0; k < Kc; ++k) {
        gpx[k] = gxr[k]*640.0f;
        gpy[k] = gyr[k]*480.0f;
        d_txv[idx*Kc+k] = gxr[k]*(float)NWc - (float)gi0;
        d_tyv[idx*Kc+k] = gyr[k]*(float)NHc - (float)gj0;
    }
    float* gt = &d_gtn[idx*20];
#pragma unroll
    for (int g = 0; g < 4; ++g) {
        gt[g*4+0] = -gpx[2*g];  gt[g*4+1] = -gpx[2*g+1];
        gt[g*4+2] = -gpy[2*g];  gt[g*4+3] = -gpy[2*g+1];
    }
    gt[16] = -gpx[8]; gt[17] = 1e18f; gt[18] = -gpy[8]; gt[19] = 1e18f;

    // best anchor by IoU on (gw, gh); first max wins (strict >)
    float gw = row[Lc-2]*(float)NWc;
    float gh = row[Lc-1]*(float)NHc;
    float best = -1.0f; int bn = 0;
#pragma unroll
    for (int a = 0; a < NAc; ++a) {
        float aw = c_anch[2*a], ah = c_anch[2*a+1];
        float mw = fminf(aw, gw), mh = fminf(ah, gh);
        float inter = mw*mh;
        float iou = inter / (aw*ah + gw*gh - inter);
        if (iou > best) { best = iou; bn = a; }
    }
    d_codeA[idx] = bn*NPIX + gj0*NWc + gi0;
    d_tclsA[idx] = row[0];

    // conf_t: gather pred box from batch (b-1 mod NB), anchor NA-1, cell (gj0, gi0)
    int bp = (b + NBc - 1) % NBc;
    const float* cb = out + ((size_t)(bp*NAc + (NAc-1))*CH)*NPIX
                          + (size_t)(gj0*NWc + gi0);
    float acc = 0.0f;
#pragma unroll
    for (int k = 0; k < Kc; ++k) {
        float xv = cb[(2*k)*NPIX];
        float yv = cb[(2*k+1)*NPIX];
        if (k == 0) { xv = sigmoidf_(xv); yv = sigmoidf_(yv); }
        float px = (xv + (float)gi0) * (1.0f/(float)NWc);
        float py = (yv + (float)gj0) * (1.0f/(float)NHc);
        float dx = (px - gxr[k]) * 640.0f;
        float dy = (py - gyr[k]) * 480.0f;
        float d2 = fmaf(dx, dx, dy*dy);
        if (d2 < TH2f) {
            float d = sqrtf(d2);
            acc += (expf(2.0f - d*0.025f) - 1.0f) * INVC0;
        }
    }
    d_conft[idx] = acc * (1.0f/(float)Kc);
}

// rare exact evaluation for one (cell,target): mean corner-conf SUM
__device__ __noinline__ float exact_conf(const float* __restrict__ cb,
                                         const float* __restrict__ tp,
                                         float fx, float fy)
{
    float acc = 0.0f;
#pragma unroll
    for (int k = 0; k < Kc; ++k) {
        float ngx = tp[(k>>1)*4 + (k&1)];
        float ngy = tp[(k>>1)*4 + 2 + (k&1)];
        float xv = cb[(2*k)*NPIX];
        float yv = cb[(2*k+1)*NPIX];
        if (k == 0) { xv = sigmoidf_(xv); yv = sigmoidf_(yv); }
        float px = fmaf(xv, SXc, fx);
        float py = fmaf(yv, SYc, fy);
        float dx = px + ngx;
        float dy = py + ngy;
        float dd2 = fmaf(dx, dx, dy*dy);
        if (dd2 < TH2f) {
            float d = sqrtf(dd2);
            acc += (expf(2.0f - d*0.025f) - 1.0f) * INVC0;
        }
    }
    return acc;
}

// rare per-object-cell / noobj epilogue
__device__ __noinline__ float cell_loss(const float* __restrict__ cb,
                                        int b, int win, int doconf, int over_sil,
                                        const float* __restrict__ sconft,
                                        const float* __restrict__ stcls)
{
    float contrib = 0.0f;
    if (win >= 0) {
        const float* txp = &d_txv[(b*NTc + win)*Kc];
        const float* typ = &d_tyv[(b*NTc + win)*Kc];
        float cl = 0.0f;
#pragma unroll
        for (int k = 0; k < Kc; ++k) {
            float xv = cb[(2*k)*NPIX];
            float yv = cb[(2*k+1)*NPIX];
            if (k == 0) { xv = sigmoidf_(xv); yv = sigmoidf_(yv); }
            float exd = xv - txp[k];
            float eyd = yv - typ[k];
            cl += exd*exd + eyd*eyd;
        }
        contrib = 0.5f*cl;

        float lg[NCc];
        float mx = -1e30f;
#pragma unroll
        for (int c = 0; c < NCc; ++c) {
            lg[c] = cb[(2*Kc+1+c)*NPIX];
            mx = fmaxf(mx, lg[c]);
        }
        float se = 0.0f;
#pragma unroll
        for (int c = 0; c < NCc; ++c) se += expf(lg[c]-mx);
        int lab = (int)stcls[win];
        lab = min(max(lab, 0), NCc-1);
        contrib += (mx + logf(se)) - lg[lab];

        if (doconf) {
            float conf = sigmoidf_(cb[(2*Kc)*NPIX]);
            float dc = conf - sconft[win];
            contrib += 0.5f*OBJf*dc*dc;
        }
    } else {
        if (doconf && !over_sil) {
            float conf = sigmoidf_(cb[(2*Kc)*NPIX]);
            contrib += 0.5f*conf*conf;
        }
    }
    return contrib;
}

// grid: (ceil(NANCH/512), NB) ; each thread handles 2 cells (tid, tid+256)
__global__ __launch_bounds__(256, 3)
void region_main(const float* __restrict__ out,
                 const int*   __restrict__ ep,
                 float* __restrict__ loss)
{
    int b   = blockIdx.y;
    int tid = threadIdx.x;
    int cellA = blockIdx.x*512 + tid;
    int cellB = cellA + 256;

    __shared__ __align__(16) float sgt[NTc*20];
    __shared__ float sconft[NTc], stcls[NTc];
    __shared__ int   scode[NTc];
    __shared__ uint  sbm[NBMW];
    __shared__ float wred[8];
    __shared__ int   snv;

    {
        const float4* src = (const float4*)&d_gtn[b*NTc*20];
        float4* dst = (float4*)sgt;
        for (int i2 = tid; i2 < NTc*20/4; i2 += 256) dst[i2] = src[i2];
    }
    if (tid < NBMW) sbm[tid] = 0u;
    if (tid == 0) snv = d_nvalid[b];
    if (tid < NTc) {
        sconft[tid] = d_conft[b*NTc + tid];
        stcls[tid]  = d_tclsA[b*NTc + tid];
        scode[tid]  = d_codeA[b*NTc + tid];
    }
    __syncthreads();      // bitmap fully zeroed + scode/snv visible
    if (tid < NTc && tid < snv) {
        int code = scode[tid];
        atomicOr(&sbm[code >> 5], 1u << (code & 31));
    }
    __syncthreads();

    int doconf = (ep[0] > 15) ? 1 : 0;
    int actA = (cellA < NANCH), actB = (cellB < NANCH);

    // per-cell packed state: pxp/pyp[5] each (corner pairs 01,23,45,67,(8,pad))
    ull pxA[5], pyA[5], pxB[5], pyB[5];
    const float* cbA = out;
    const float* cbB = out;
    float fxA = 0.f, fyA = 0.f, fxB = 0.f, fyB = 0.f;

    {
        ull big = pack2(1e30f, 1e30f);
#pragma unroll
        for (int g = 0; g < 5; ++g) { pxA[g]=big; pyA[g]=big; pxB[g]=big; pyB[g]=big; }
    }
    if (actA) {
        int a = cellA / NPIX, pos = cellA - a*NPIX;
        int jj = pos / NWc, ii = pos - jj*NWc;
        cbA = out + ((size_t)(b*NAc + a)*CH)*NPIX + (size_t)pos;
        fxA = (float)ii * SXc; fyA = (float)jj * SYc;
        float px[Kc], py[Kc];
#pragma unroll
        for (int k = 0; k < Kc; ++k) {
            float xv = cbA[(2*k)*NPIX];
            float yv = cbA[(2*k+1)*NPIX];
            if (k == 0) { xv = sigmoidf_(xv); yv = sigmoidf_(yv); }
            px[k] = fmaf(xv, SXc, fxA);
            py[k] = fmaf(yv, SYc, fyA);
        }
#pragma unroll
        for (int g = 0; g < 4; ++g) {
            pxA[g] = pack2(px[2*g], px[2*g+1]);
            pyA[g] = pack2(py[2*g], py[2*g+1]);
        }
        pxA[4] = pack2(px[8], 0.0f);
        pyA[4] = pack2(py[8], 0.0f);
    }
    if (actB) {
        int a = cellB / NPIX, pos = cellB - a*NPIX;
        int jj = pos / NWc, ii = pos - jj*NWc;
        cbB = out + ((size_t)(b*NAc + a)*CH)*NPIX + (size_t)pos;
        fxB = (float)ii * SXc; fyB = (float)jj * SYc;
        float px[Kc], py[Kc];
#pragma unroll
        for (int k = 0; k < Kc; ++k) {
            float xv = cbB[(2*k)*NPIX];
            float yv = cbB[(2*k+1)*NPIX];
            if (k == 0) { xv = sigmoidf_(xv); yv = sigmoidf_(yv); }
            px[k] = fmaf(xv, SXc, fxB);
            py[k] = fmaf(yv, SYc, fyB);
        }
#pragma unroll
        for (int g = 0; g < 4; ++g) {
            pxB[g] = pack2(px[2*g], px[2*g+1]);
            pyB[g] = pack2(py[2*g], py[2*g+1]);
        }
        pxB[4] = pack2(px[8], 0.0f);
        pyB[4] = pack2(py[8], 0.0f);
    }

    const ull nTH2 = pack2(-TH2f, -TH2f);
    int nv = snv;
    float mA = 0.0f, mB = 0.0f;

    for (int t = 0; t < nv; ++t) {
        const ulonglong2* q = (const ulonglong2*)&sgt[t*20];
        ulonglong2 q0 = q[0], q1 = q[1], q2 = q[2], q3 = q[3], q4 = q[4];
        // qg.x = (-gx pair), qg.y = (-gy pair)

        ull a0 = dist2m(pxA[0], pyA[0], q0.x, q0.y, nTH2);
        ull a1 = dist2m(pxA[1], pyA[1], q1.x, q1.y, nTH2);
        ull a2 = dist2m(pxA[2], pyA[2], q2.x, q2.y, nTH2);
        ull a3 = dist2m(pxA[3], pyA[3], q3.x, q3.y, nTH2);
        ull a4 = dist2m(pxA[4], pyA[4], q4.x, q4.y, nTH2);
        uint cntA = sgn2(a0) + sgn2(a1) + sgn2(a2) + sgn2(a3) + sgn2(a4);

        ull b0 = dist2m(pxB[0], pyB[0], q0.x, q0.y, nTH2);
        ull b1 = dist2m(pxB[1], pyB[1], q1.x, q1.y, nTH2);
        ull b2 = dist2m(pxB[2], pyB[2], q2.x, q2.y, nTH2);
        ull b3 = dist2m(pxB[3], pyB[3], q3.x, q3.y, nTH2);
        ull b4 = dist2m(pxB[4], pyB[4], q4.x, q4.y, nTH2);
        uint cntB = sgn2(b0) + sgn2(b1) + sgn2(b2) + sgn2(b3) + sgn2(b4);

        // mean-conf > 0.6 (sum > 5.4) requires >= 6 corners within TH
        // (each corner conf <= 1). Exact eval only then (warp-rare).
        if (cntA >= 6) mA = fmaxf(mA, exact_conf(cbA, &sgt[t*20], fxA, fyA));
        if (cntB >= 6) mB = fmaxf(mB, exact_conf(cbB, &sgt[t*20], fxB, fyB));
    }

    float contrib = 0.0f;
    if (actA) {
        int over = (mA * (1.0f/(float)Kc)) > SILf;
        int win = -1;
        if (sbm[cellA >> 5] & (1u << (cellA & 31))) {
            for (int t = nv-1; t >= 0; --t)
                if (scode[t] == cellA) { win = t; break; }
        }
        if (win >= 0 || (doconf && !over))
            contrib += cell_loss(cbA, b, win, doconf, over, sconft, stcls);
    }
    if (actB) {
        int over = (mB * (1.0f/(float)Kc)) > SILf;
        int win = -1;
        if (sbm[cellB >> 5] & (1u << (cellB & 31))) {
            for (int t = nv-1; t >= 0; --t)
                if (scode[t] == cellB) { win = t; break; }
        }
        if (win >= 0 || (doconf && !over))
            contrib += cell_loss(cbB, b, win, doconf, over, sconft, stcls);
    }

    // warp-shuffle reduction + one atomic per block
#pragma unroll
    for (int off = 16; off > 0; off >>= 1)
        contrib += __shfl_down_sync(0xFFFFFFFFu, contrib, off);
    int lane = tid & 31, wid = tid >> 5;
    if (lane == 0) wred[wid] = contrib;
    __syncthreads();
    if (tid < 8) {
        float v = wred[tid];
#pragma unroll
        for (int off = 4; off > 0; off >>= 1)
            v += __shfl_down_sync(0xFFu, v, off);
        if (tid == 0) atomicAdd(loss, v);
    }
}

extern "C" void kernel_launch(void* const* d_in, const int* in_sizes, int n_in,
                              void* d_out, int out_size)
{
    const float* out = (const float*)d_in[0];
    const float* tgt = (const float*)d_in[1];
    const int*   ep  = (const int*)d_in[2];
    float* loss = (float*)d_out;

    region_prep<<<NBc, 64>>>(out, tgt, loss);
    dim3 g((NANCH + 511)/512, NBc);
    region_main<<<g, 256>>>(out, ep, loss);
}

// round 6
// speedup vs baseline: 1.0272x; 1.0272x over previous
#include <cuda_runtime.h>

// Problem constants
#define Kc    9
#define NCc   13
#define NAc   5
#define NBc   128
#define NHc   26
#define NWc   26
#define NTc   50
#define Lc    21          // 2K+3
#define NPIX  (NHc*NWc)   // 676
#define NANCH (NAc*NHc*NWc) // 3380
#define CH    (2*Kc+1+NCc) // 32
#define NBMW  106          // ceil(3380/32)

#define THf     80.0f
#define TH2f    6400.0f
#define SILf    0.6f
#define OBJf    5.0f
// 1/(exp(2)-1)
#define INVC0   0.15651764274966574f

#define SXc (640.0f/26.0f)
#define SYc (480.0f/26.0f)

typedef unsigned long long ull;
typedef unsigned int uint;

// Scratch (device globals — no allocation allowed)
// Per (b,t): 20 floats = 5 float4; group g (corner pair 2g,2g+1):
//   [g*4+0]=-gx_{2g}  [g*4+1]=-gx_{2g+1}  [g*4+2]=-gy_{2g}  [g*4+3]=-gy_{2g+1]
// group 4 = (corner 8, pad): pad value 1e18 (never inside)
__device__ __align__(16) float d_gtn[NBc*NTc*20];
__device__ float d_txv[NBc*NTc*Kc];
__device__ float d_tyv[NBc*NTc*Kc];
__device__ float d_conft[NBc*NTc];
__device__ float d_tclsA[NBc*NTc];
__device__ int   d_codeA[NBc*NTc];
__device__ int   d_nvalid[NBc];

__constant__ float c_anch[10] = {1.482f,2.2412f,2.0501f,3.1265f,2.3946f,
                                 4.6891f,3.1018f,3.991f,3.4879f,5.8851f};

__device__ __forceinline__ float sigmoidf_(float x) { return 1.0f/(1.0f+expf(-x)); }

__device__ __forceinline__ ull pack2(float lo, float hi) {
    ull r;
    asm("mov.b64 %0, {%1, %2};" : "=l"(r) : "f"(lo), "f"(hi));
    return r;
}
__device__ __forceinline__ ull fma2_(ull a, ull b, ull c) {
    ull d;
    asm("fma.rn.f32x2 %0, %1, %2, %3;" : "=l"(d) : "l"(a), "l"(b), "l"(c));
    return d;
}
__device__ __forceinline__ ull add2_(ull a, ull b) {
    ull d;
    asm("add.rn.f32x2 %0, %1, %2;" : "=l"(d) : "l"(a), "l"(b));
    return d;
}
// d^2 - TH^2 for a corner pair (direct form)
__device__ __forceinline__ ull dist2m(ull px, ull py, ull ngx, ull ngy, ull nTH2) {
    ull dx = add2_(px, ngx);
    ull dy = add2_(py, ngy);
    return fma2_(dx, dx, fma2_(dy, dy, nTH2));
}
// sign bytes of the two packed floats in d -> bytes0,1 as 0xFF/0x00
__device__ __forceinline__ uint prmt_sgn(ull d) {
    uint lo = (uint)d, hi = (uint)(d >> 32), r;
    asm("prmt.b32 %0, %1, %2, 0x000000FB;" : "=r"(r) : "r"(lo), "r"(hi));
    return r;
}
// acc -= (#sign bytes among bytes 0,1 of s)
__device__ __forceinline__ int dp4a_cnt(uint s, int acc) {
    int r;
    asm("dp4a.s32.s32 %0, %1, %2, %3;" : "=r"(r) : "r"(s), "r"(0x00000101), "r"(acc));
    return r;
}

// One block per batch; thread t handles target t. Also zeroes the loss scalar.
__global__ void region_prep(const float* __restrict__ out,
                            const float* __restrict__ tgt,
                            float* __restrict__ loss)
{
    int b = blockIdx.x;
    int t = threadIdx.x;
    if (b == 0 && t == 0) loss[0] = 0.0f;

    __shared__ int sflag[NTc];
    if (t < NTc)
        sflag[t] = (tgt[(size_t)b*NTc*Lc + (size_t)t*Lc + 1] != 0.0f) ? 1 : 0;
    __syncthreads();
    if (t == 0) {
        int nv = NTc;
        for (int q = 0; q < NTc; ++q) if (!sflag[q]) { nv = q; break; }
        d_nvalid[b] = nv;
    }
    if (t >= NTc) return;

    const float* row = tgt + (size_t)b*NTc*Lc + (size_t)t*Lc;
    float gxr[Kc], gyr[Kc];
#pragma unroll
    for (int k = 0; k < Kc; ++k) { gxr[k] = row[1+2*k]; gyr[k] = row[2+2*k]; }

    int gi0 = (int)floorf(gxr[0]*(float)NWc);
    int gj0 = (int)floorf(gyr[0]*(float)NHc);
    gi0 = min(max(gi0, 0), NWc-1);
    gj0 = min(max(gj0, 0), NHc-1);

    int idx = b*NTc + t;

    float gpx[Kc], gpy[Kc];
#pragma unroll
    for (int k = 0; k < Kc; ++k) {
        gpx[k] = gxr[k]*640.0f;
        gpy[k] = gyr[k]*480.0f;
        d_txv[idx*Kc+k] = gxr[k]*(float)NWc - (float)gi0;
        d_tyv[idx*Kc+k] = gyr[k]*(float)NHc - (float)gj0;
    }
    float* gt = &d_gtn[idx*20];
#pragma unroll
    for (int g = 0; g < 4; ++g) {
        gt[g*4+0] = -gpx[2*g];  gt[g*4+1] = -gpx[2*g+1];
        gt[g*4+2] = -gpy[2*g];  gt[g*4+3] = -gpy[2*g+1];
    }
    gt[16] = -gpx[8]; gt[17] = 1e18f; gt[18] = -gpy[8]; gt[19] = 1e18f;

    // best anchor by IoU on (gw, gh); first max wins (strict >)
    float gw = row[Lc-2]*(float)NWc;
    float gh = row[Lc-1]*(float)NHc;
    float best = -1.0f; int bn = 0;
#pragma unroll
    for (int a = 0; a < NAc; ++a) {
        float aw = c_anch[2*a], ah = c_anch[2*a+1];
        float mw = fminf(aw, gw), mh = fminf(ah, gh);
        float inter = mw*mh;
        float iou = inter / (aw*ah + gw*gh - inter);
        if (iou > best) { best = iou; bn = a; }
    }
    d_codeA[idx] = bn*NPIX + gj0*NWc + gi0;
    d_tclsA[idx] = row[0];

    // conf_t: gather pred box from batch (b-1 mod NB), anchor NA-1, cell (gj0, gi0)
    int bp = (b + NBc - 1) % NBc;
    const float* cb = out + ((size_t)(bp*NAc + (NAc-1))*CH)*NPIX
                          + (size_t)(gj0*NWc + gi0);
    float acc = 0.0f;
#pragma unroll
    for (int k = 0; k < Kc; ++k) {
        float xv = cb[(2*k)*NPIX];
        float yv = cb[(2*k+1)*NPIX];
        if (k == 0) { xv = sigmoidf_(xv); yv = sigmoidf_(yv); }
        float px = (xv + (float)gi0) * (1.0f/(float)NWc);
        float py = (yv + (float)gj0) * (1.0f/(float)NHc);
        float dx = (px - gxr[k]) * 640.0f;
        float dy = (py - gyr[k]) * 480.0f;
        float d2 = fmaf(dx, dx, dy*dy);
        if (d2 < TH2f) {
            float d = sqrtf(d2);
            acc += (expf(2.0f - d*0.025f) - 1.0f) * INVC0;
        }
    }
    d_conft[idx] = acc * (1.0f/(float)Kc);
}

// rare exact evaluation for one (cell,target): mean corner-conf SUM
__device__ __noinline__ float exact_conf(const float* __restrict__ cb,
                                         const float* __restrict__ tp,
                                         float fx, float fy)
{
    float acc = 0.0f;
#pragma unroll
    for (int k = 0; k < Kc; ++k) {
        float ngx = tp[(k>>1)*4 + (k&1)];
        float ngy = tp[(k>>1)*4 + 2 + (k&1)];
        float xv = cb[(2*k)*NPIX];
        float yv = cb[(2*k+1)*NPIX];
        if (k == 0) { xv = sigmoidf_(xv); yv = sigmoidf_(yv); }
        float px = fmaf(xv, SXc, fx);
        float py = fmaf(yv, SYc, fy);
        float dx = px + ngx;
        float dy = py + ngy;
        float dd2 = fmaf(dx, dx, dy*dy);
        if (dd2 < TH2f) {
            float d = sqrtf(dd2);
            acc += (expf(2.0f - d*0.025f) - 1.0f) * INVC0;
        }
    }
    return acc;
}

// rare per-object-cell / noobj epilogue
__device__ __noinline__ float cell_loss(const float* __restrict__ cb,
                                        int b, int win, int doconf, int over_sil,
                                        const float* __restrict__ sconft,
                                        const float* __restrict__ stcls)
{
    float contrib = 0.0f;
    if (win >= 0) {
        const float* txp = &d_txv[(b*NTc + win)*Kc];
        const float* typ = &d_tyv[(b*NTc + win)*Kc];
        float cl = 0.0f;
#pragma unroll
        for (int k = 0; k < Kc; ++k) {
            float xv = cb[(2*k)*NPIX];
            float yv = cb[(2*k+1)*NPIX];
            if (k == 0) { xv = sigmoidf_(xv); yv = sigmoidf_(yv); }
            float exd = xv - txp[k];
            float eyd = yv - typ[k];
            cl += exd*exd + eyd*eyd;
        }
        contrib = 0.5f*cl;

        float lg[NCc];
        float mx = -1e30f;
#pragma unroll
        for (int c = 0; c < NCc; ++c) {
            lg[c] = cb[(2*Kc+1+c)*NPIX];
            mx = fmaxf(mx, lg[c]);
        }
        float se = 0.0f;
#pragma unroll
        for (int c = 0; c < NCc; ++c) se += expf(lg[c]-mx);
        int lab = (int)stcls[win];
        lab = min(max(lab, 0), NCc-1);
        contrib += (mx + logf(se)) - lg[lab];

        if (doconf) {
            float conf = sigmoidf_(cb[(2*Kc)*NPIX]);
            float dc = conf - sconft[win];
            contrib += 0.5f*OBJf*dc*dc;
        }
    } else {
        if (doconf && !over_sil) {
            float conf = sigmoidf_(cb[(2*Kc)*NPIX]);
            contrib += 0.5f*conf*conf;
        }
    }
    return contrib;
}

// grid: (ceil(NANCH/512), NB) ; each thread handles 2 cells (tid, tid+256)
__global__ __launch_bounds__(256, 3)
void region_main(const float* __restrict__ out,
                 const int*   __restrict__ ep,
                 float* __restrict__ loss)
{
    int b   = blockIdx.y;
    int tid = threadIdx.x;
    int cellA = blockIdx.x*512 + tid;
    int cellB = cellA + 256;

    __shared__ __align__(16) float sgt[NTc*20];
    __shared__ float sconft[NTc], stcls[NTc];
    __shared__ int   scode[NTc];
    __shared__ uint  sbm[NBMW];
    __shared__ float wred[8];
    __shared__ int   snv;

    {
        const float4* src = (const float4*)&d_gtn[b*NTc*20];
        float4* dst = (float4*)sgt;
        for (int i2 = tid; i2 < NTc*20/4; i2 += 256) dst[i2] = src[i2];
    }
    if (tid < NBMW) sbm[tid] = 0u;
    if (tid == 0) snv = d_nvalid[b];
    if (tid < NTc) {
        sconft[tid] = d_conft[b*NTc + tid];
        stcls[tid]  = d_tclsA[b*NTc + tid];
        scode[tid]  = d_codeA[b*NTc + tid];
    }
    __syncthreads();      // bitmap fully zeroed + scode/snv visible
    if (tid < NTc && tid < snv) {
        int code = scode[tid];
        atomicOr(&sbm[code >> 5], 1u << (code & 31));
    }
    __syncthreads();

    int doconf = (ep[0] > 15) ? 1 : 0;
    int actA = (cellA < NANCH), actB = (cellB < NANCH);

    // per-cell packed state: pxp/pyp[5] each (corner pairs 01,23,45,67,(8,pad))
    ull pxA[5], pyA[5], pxB[5], pyB[5];
    const float* cbA = out;
    const float* cbB = out;
    float fxA = 0.f, fyA = 0.f, fxB = 0.f, fyB = 0.f;

    {
        ull big = pack2(1e30f, 1e30f);
#pragma unroll
        for (int g = 0; g < 5; ++g) { pxA[g]=big; pyA[g]=big; pxB[g]=big; pyB[g]=big; }
    }
    if (actA) {
        int a = cellA / NPIX, pos = cellA - a*NPIX;
        int jj = pos / NWc, ii = pos - jj*NWc;
        cbA = out + ((size_t)(b*NAc + a)*CH)*NPIX + (size_t)pos;
        fxA = (float)ii * SXc; fyA = (float)jj * SYc;
        float px[Kc], py[Kc];
#pragma unroll
        for (int k = 0; k < Kc; ++k) {
            float xv = cbA[(2*k)*NPIX];
            float yv = cbA[(2*k+1)*NPIX];
            if (k == 0) { xv = sigmoidf_(xv); yv = sigmoidf_(yv); }
            px[k] = fmaf(xv, SXc, fxA);
            py[k] = fmaf(yv, SYc, fyA);
        }
#pragma unroll
        for (int g = 0; g < 4; ++g) {
            pxA[g] = pack2(px[2*g], px[2*g+1]);
            pyA[g] = pack2(py[2*g], py[2*g+1]);
        }
        pxA[4] = pack2(px[8], 0.0f);
        pyA[4] = pack2(py[8], 0.0f);
    }
    if (actB) {
        int a = cellB / NPIX, pos = cellB - a*NPIX;
        int jj = pos / NWc, ii = pos - jj*NWc;
        cbB = out + ((size_t)(b*NAc + a)*CH)*NPIX + (size_t)pos;
        fxB = (float)ii * SXc; fyB = (float)jj * SYc;
        float px[Kc], py[Kc];
#pragma unroll
        for (int k = 0; k < Kc; ++k) {
            float xv = cbB[(2*k)*NPIX];
            float yv = cbB[(2*k+1)*NPIX];
            if (k == 0) { xv = sigmoidf_(xv); yv = sigmoidf_(yv); }
            px[k] = fmaf(xv, SXc, fxB);
            py[k] = fmaf(yv, SYc, fyB);
        }
#pragma unroll
        for (int g = 0; g < 4; ++g) {
            pxB[g] = pack2(px[2*g], px[2*g+1]);
            pyB[g] = pack2(py[2*g], py[2*g+1]);
        }
        pxB[4] = pack2(px[8], 0.0f);
        pyB[4] = pack2(py[8], 0.0f);
    }

    const ull nTH2 = pack2(-TH2f, -TH2f);
    int nv = snv;
    float mA = 0.0f, mB = 0.0f;

#pragma unroll 2
    for (int t = 0; t < nv; ++t) {
        const ulonglong2* q = (const ulonglong2*)&sgt[t*20];
        ulonglong2 q0 = q[0], q1 = q[1], q2 = q[2], q3 = q[3], q4 = q[4];
        // qg.x = (-gx pair), qg.y = (-gy pair)

        ull a0 = dist2m(pxA[0], pyA[0], q0.x, q0.y, nTH2);
        ull a1 = dist2m(pxA[1], pyA[1], q1.x, q1.y, nTH2);
        ull a2 = dist2m(pxA[2], pyA[2], q2.x, q2.y, nTH2);
        ull a3 = dist2m(pxA[3], pyA[3], q3.x, q3.y, nTH2);
        ull a4 = dist2m(pxA[4], pyA[4], q4.x, q4.y, nTH2);
        int accA = 0;
        accA = dp4a_cnt(prmt_sgn(a0), accA);
        accA = dp4a_cnt(prmt_sgn(a1), accA);
        accA = dp4a_cnt(prmt_sgn(a2), accA);
        accA = dp4a_cnt(prmt_sgn(a3), accA);
        accA = dp4a_cnt(prmt_sgn(a4), accA);

        ull b0 = dist2m(pxB[0], pyB[0], q0.x, q0.y, nTH2);
        ull b1 = dist2m(pxB[1], pyB[1], q1.x, q1.y, nTH2);
        ull b2 = dist2m(pxB[2], pyB[2], q2.x, q2.y, nTH2);
        ull b3 = dist2m(pxB[3], pyB[3], q3.x, q3.y, nTH2);
        ull b4 = dist2m(pxB[4], pyB[4], q4.x, q4.y, nTH2);
        int accB = 0;
        accB = dp4a_cnt(prmt_sgn(b0), accB);
        accB = dp4a_cnt(prmt_sgn(b1), accB);
        accB = dp4a_cnt(prmt_sgn(b2), accB);
        accB = dp4a_cnt(prmt_sgn(b3), accB);
        accB = dp4a_cnt(prmt_sgn(b4), accB);

        // acc = -(#corners inside). mean-conf > 0.6 (sum > 5.4) requires
        // >= 6 corners within TH (each corner conf <= 1). Exact eval rare.
        if (min(accA, accB) <= -6) {
            if (accA <= -6) mA = fmaxf(mA, exact_conf(cbA, &sgt[t*20], fxA, fyA));
            if (accB <= -6) mB = fmaxf(mB, exact_conf(cbB, &sgt[t*20], fxB, fyB));
        }
    }

    float contrib = 0.0f;
    if (actA) {
        int over = (mA * (1.0f/(float)Kc)) > SILf;
        int win = -1;
        if (sbm[cellA >> 5] & (1u << (cellA & 31))) {
            for (int t = nv-1; t >= 0; --t)
                if (scode[t] == cellA) { win = t; break; }
        }
        if (win >= 0 || (doconf && !over))
            contrib += cell_loss(cbA, b, win, doconf, over, sconft, stcls);
    }
    if (actB) {
        int over = (mB * (1.0f/(float)Kc)) > SILf;
        int win = -1;
        if (sbm[cellB >> 5] & (1u << (cellB & 31))) {
            for (int t = nv-1; t >= 0; --t)
                if (scode[t] == cellB) { win = t; break; }
        }
        if (win >= 0 || (doconf && !over))
            contrib += cell_loss(cbB, b, win, doconf, over, sconft, stcls);
    }

    // warp-shuffle reduction + one atomic per block
#pragma unroll
    for (int off = 16; off > 0; off >>= 1)
        contrib += __shfl_down_sync(0xFFFFFFFFu, contrib, off);
    int lane = tid & 31, wid = tid >> 5;
    if (lane == 0) wred[wid] = contrib;
    __syncthreads();
    if (tid < 8) {
        float v = wred[tid];
#pragma unroll
        for (int off = 4; off > 0; off >>= 1)
            v += __shfl_down_sync(0xFFu, v, off);
        if (tid == 0) atomicAdd(loss, v);
    }
}

extern "C" void kernel_launch(void* const* d_in, const int* in_sizes, int n_in,
                              void* d_out, int out_size)
{
    const float* out = (const float*)d_in[0];
    const float* tgt = (const float*)d_in[1];
    const int*   ep  = (const int*)d_in[2];
    float* loss = (float*)d_out;

    region_prep<<<NBc, 64>>>(out, tgt, loss);
    dim3 g((NANCH + 511)/512, NBc);
    region_main<<<g, 256>>>(out, ep, loss);
}

// round 7
// speedup vs baseline: 1.0595x; 1.0314x over previous
#include <cuda_runtime.h>

// Problem constants
#define Kc    9
#define NCc   13
#define NAc   5
#define NBc   128
#define NHc   26
#define NWc   26
#define NTc   50
#define Lc    21          // 2K+3
#define NPIX  (NHc*NWc)   // 676
#define NANCH (NAc*NHc*NWc) // 3380
#define CH    (2*Kc+1+NCc) // 32
#define NBMW  106          // ceil(3380/32)

#define THf     80.0f
#define TH2f    6400.0f
#define SILf    0.6f
#define OBJf    5.0f
// 1/(exp(2)-1)
#define INVC0   0.15651764274966574f

#define SXc (640.0f/26.0f)
#define SYc (480.0f/26.0f)

typedef unsigned long long ull;
typedef unsigned int uint;

// Scratch (device globals — no allocation allowed)
// Per (b,t): 20 floats = 5 float4; group g in 0..3 (corner pair 2g,2g+1):
//   [g*4+0]=-gx_{2g}  [g*4+1]=-gx_{2g+1}  [g*4+2]=-gy_{2g}  [g*4+3]=-gy_{2g+1}
// group 4 = corner 8 DUPLICATED: [16]=-gx8 [17]=-gx8 [18]=-gy8 [19]=-gy8
// (lets one packed op evaluate corner 8 for two different cells at once)
__device__ __align__(16) float d_gtn[NBc*NTc*20];
__device__ float d_txv[NBc*NTc*Kc];
__device__ float d_tyv[NBc*NTc*Kc];
__device__ float d_conft[NBc*NTc];
__device__ float d_tclsA[NBc*NTc];
__device__ int   d_codeA[NBc*NTc];
__device__ int   d_nvalid[NBc];

__constant__ float c_anch[10] = {1.482f,2.2412f,2.0501f,3.1265f,2.3946f,
                                 4.6891f,3.1018f,3.991f,3.4879f,5.8851f};

__device__ __forceinline__ float sigmoidf_(float x) { return 1.0f/(1.0f+expf(-x)); }

__device__ __forceinline__ ull pack2(float lo, float hi) {
    ull r;
    asm("mov.b64 %0, {%1, %2};" : "=l"(r) : "f"(lo), "f"(hi));
    return r;
}
__device__ __forceinline__ ull fma2_(ull a, ull b, ull c) {
    ull d;
    asm("fma.rn.f32x2 %0, %1, %2, %3;" : "=l"(d) : "l"(a), "l"(b), "l"(c));
    return d;
}
__device__ __forceinline__ ull add2_(ull a, ull b) {
    ull d;
    asm("add.rn.f32x2 %0, %1, %2;" : "=l"(d) : "l"(a), "l"(b));
    return d;
}
// d^2 - TH^2 for a corner pair (direct form)
__device__ __forceinline__ ull dist2m(ull px, ull py, ull ngx, ull ngy, ull nTH2) {
    ull dx = add2_(px, ngx);
    ull dy = add2_(py, ngy);
    return fma2_(dx, dx, fma2_(dy, dy, nTH2));
}
// sign bytes of the two packed floats in d -> bytes0,1 as 0xFF/0x00
__device__ __forceinline__ uint prmt_sgn(ull d) {
    uint lo = (uint)d, hi = (uint)(d >> 32), r;
    asm("prmt.b32 %0, %1, %2, 0x000000FB;" : "=r"(r) : "r"(lo), "r"(hi));
    return r;
}
// acc += dot(sign bytes, sel) (sel selects which bytes count, -1 per inside)
__device__ __forceinline__ int dp4a_sel(uint s, uint sel, int acc) {
    int r;
    asm("dp4a.s32.s32 %0, %1, %2, %3;" : "=r"(r) : "r"(s), "r"(sel), "r"(acc));
    return r;
}

// One block per batch; thread t handles target t. Also zeroes the loss scalar.
__global__ void region_prep(const float* __restrict__ out,
                            const float* __restrict__ tgt,
                            float* __restrict__ loss)
{
    int b = blockIdx.x;
    int t = threadIdx.x;
    if (b == 0 && t == 0) loss[0] = 0.0f;

    __shared__ int sflag[NTc];
    if (t < NTc)
        sflag[t] = (tgt[(size_t)b*NTc*Lc + (size_t)t*Lc + 1] != 0.0f) ? 1 : 0;
    __syncthreads();
    if (t == 0) {
        int nv = NTc;
        for (int q = 0; q < NTc; ++q) if (!sflag[q]) { nv = q; break; }
        d_nvalid[b] = nv;
    }
    if (t >= NTc) return;

    const float* row = tgt + (size_t)b*NTc*Lc + (size_t)t*Lc;
    float gxr[Kc], gyr[Kc];
#pragma unroll
    for (int k = 0; k < Kc; ++k) { gxr[k] = row[1+2*k]; gyr[k] = row[2+2*k]; }

    int gi0 = (int)floorf(gxr[0]*(float)NWc);
    int gj0 = (int)floorf(gyr[0]*(float)NHc);
    gi0 = min(max(gi0, 0), NWc-1);
    gj0 = min(max(gj0, 0), NHc-1);

    int idx = b*NTc + t;

    float gpx[Kc], gpy[Kc];
#pragma unroll
    for (int k = 0; k < Kc; ++k) {
        gpx[k] = gxr[k]*640.0f;
        gpy[k] = gyr[k]*480.0f;
        d_txv[idx*Kc+k] = gxr[k]*(float)NWc - (float)gi0;
        d_tyv[idx*Kc+k] = gyr[k]*(float)NHc - (float)gj0;
    }
    float* gt = &d_gtn[idx*20];
#pragma unroll
    for (int g = 0; g < 4; ++g) {
        gt[g*4+0] = -gpx[2*g];  gt[g*4+1] = -gpx[2*g+1];
        gt[g*4+2] = -gpy[2*g];  gt[g*4+3] = -gpy[2*g+1];
    }
    gt[16] = -gpx[8]; gt[17] = -gpx[8]; gt[18] = -gpy[8]; gt[19] = -gpy[8];

    // best anchor by IoU on (gw, gh); first max wins (strict >)
    float gw = row[Lc-2]*(float)NWc;
    float gh = row[Lc-1]*(float)NHc;
    float best = -1.0f; int bn = 0;
#pragma unroll
    for (int a = 0; a < NAc; ++a) {
        float aw = c_anch[2*a], ah = c_anch[2*a+1];
        float mw = fminf(aw, gw), mh = fminf(ah, gh);
        float inter = mw*mh;
        float iou = inter / (aw*ah + gw*gh - inter);
        if (iou > best) { best = iou; bn = a; }
    }
    d_codeA[idx] = bn*NPIX + gj0*NWc + gi0;
    d_tclsA[idx] = row[0];

    // conf_t: gather pred box from batch (b-1 mod NB), anchor NA-1, cell (gj0, gi0)
    int bp = (b + NBc - 1) % NBc;
    const float* cb = out + ((size_t)(bp*NAc + (NAc-1))*CH)*NPIX
                          + (size_t)(gj0*NWc + gi0);
    float acc = 0.0f;
#pragma unroll
    for (int k = 0; k < Kc; ++k) {
        float xv = cb[(2*k)*NPIX];
        float yv = cb[(2*k+1)*NPIX];
        if (k == 0) { xv = sigmoidf_(xv); yv = sigmoidf_(yv); }
        float px = (xv + (float)gi0) * (1.0f/(float)NWc);
        float py = (yv + (float)gj0) * (1.0f/(float)NHc);
        float dx = (px - gxr[k]) * 640.0f;
        float dy = (py - gyr[k]) * 480.0f;
        float d2 = fmaf(dx, dx, dy*dy);
        if (d2 < TH2f) {
            float d = sqrtf(d2);
            acc += (expf(2.0f - d*0.025f) - 1.0f) * INVC0;
        }
    }
    d_conft[idx] = acc * (1.0f/(float)Kc);
}

// rare exact evaluation for one (cell,target): mean corner-conf SUM
__device__ __noinline__ float exact_conf(const float* __restrict__ cb,
                                         const float* __restrict__ tp,
                                         int cell)
{
    int a = cell / NPIX, pos = cell - a*NPIX;
    int jj = pos / NWc, ii = pos - jj*NWc;
    float fx = (float)ii * SXc, fy = (float)jj * SYc;
    float acc = 0.0f;
#pragma unroll
    for (int k = 0; k < Kc; ++k) {
        float ngx = tp[(k>>1)*4 + (k&1)];
        float ngy = tp[(k>>1)*4 + 2 + (k&1)];
        float xv = cb[(2*k)*NPIX];
        float yv = cb[(2*k+1)*NPIX];
        if (k == 0) { xv = sigmoidf_(xv); yv = sigmoidf_(yv); }
        float px = fmaf(xv, SXc, fx);
        float py = fmaf(yv, SYc, fy);
        float dx = px + ngx;
        float dy = py + ngy;
        float dd2 = fmaf(dx, dx, dy*dy);
        if (dd2 < TH2f) {
            float d = sqrtf(dd2);
            acc += (expf(2.0f - d*0.025f) - 1.0f) * INVC0;
        }
    }
    return acc;
}

// rare per-object-cell / noobj epilogue
__device__ __noinline__ float cell_loss(const float* __restrict__ cb,
                                        int b, int win, int doconf, int over_sil,
                                        const float* __restrict__ sconft,
                                        const float* __restrict__ stcls)
{
    float contrib = 0.0f;
    if (win >= 0) {
        const float* txp = &d_txv[(b*NTc + win)*Kc];
        const float* typ = &d_tyv[(b*NTc + win)*Kc];
        float cl = 0.0f;
#pragma unroll
        for (int k = 0; k < Kc; ++k) {
            float xv = cb[(2*k)*NPIX];
            float yv = cb[(2*k+1)*NPIX];
            if (k == 0) { xv = sigmoidf_(xv); yv = sigmoidf_(yv); }
            float exd = xv - txp[k];
            float eyd = yv - typ[k];
            cl += exd*exd + eyd*eyd;
        }
        contrib = 0.5f*cl;

        float lg[NCc];
        float mx = -1e30f;
#pragma unroll
        for (int c = 0; c < NCc; ++c) {
            lg[c] = cb[(2*Kc+1+c)*NPIX];
            mx = fmaxf(mx, lg[c]);
        }
        float se = 0.0f;
#pragma unroll
        for (int c = 0; c < NCc; ++c) se += expf(lg[c]-mx);
        int lab = (int)stcls[win];
        lab = min(max(lab, 0), NCc-1);
        contrib += (mx + logf(se)) - lg[lab];

        if (doconf) {
            float conf = sigmoidf_(cb[(2*Kc)*NPIX]);
            float dc = conf - sconft[win];
            contrib += 0.5f*OBJf*dc*dc;
        }
    } else {
        if (doconf && !over_sil) {
            float conf = sigmoidf_(cb[(2*Kc)*NPIX]);
            contrib += 0.5f*conf*conf;
        }
    }
    return contrib;
}

// fill packed corner pairs (groups 0..3) + scalar corner 8 for one cell
__device__ __forceinline__ void cell_setup(const float* __restrict__ cb,
                                           int cell, ull* px, ull* py,
                                           float& px8, float& py8)
{
    int a = cell / NPIX, pos = cell - a*NPIX;
    int jj = pos / NWc, ii = pos - jj*NWc;
    float fx = (float)ii * SXc, fy = (float)jj * SYc;
    float pxs[Kc], pys[Kc];
#pragma unroll
    for (int k = 0; k < Kc; ++k) {
        float xv = cb[(2*k)*NPIX];
        float yv = cb[(2*k+1)*NPIX];
        if (k == 0) { xv = sigmoidf_(xv); yv = sigmoidf_(yv); }
        pxs[k] = fmaf(xv, SXc, fx);
        pys[k] = fmaf(yv, SYc, fy);
    }
#pragma unroll
    for (int g = 0; g < 4; ++g) {
        px[g] = pack2(pxs[2*g], pxs[2*g+1]);
        py[g] = pack2(pys[2*g], pys[2*g+1]);
    }
    px8 = pxs[8]; py8 = pys[8];
}

// grid: (ceil(NANCH/512), NB) ; each thread handles 2 cells (tid, tid+256)
__global__ __launch_bounds__(256, 4)
void region_main(const float* __restrict__ out,
                 const int*   __restrict__ ep,
                 float* __restrict__ loss)
{
    int b   = blockIdx.y;
    int tid = threadIdx.x;
    int cellA = blockIdx.x*512 + tid;
    int cellB = cellA + 256;

    __shared__ __align__(16) float sgt[NTc*20];
    __shared__ float sconft[NTc], stcls[NTc];
    __shared__ int   scode[NTc];
    __shared__ uint  sbm[NBMW];
    __shared__ float wred[8];
    __shared__ int   snv;

    {
        const float4* src = (const float4*)&d_gtn[b*NTc*20];
        float4* dst = (float4*)sgt;
        for (int i2 = tid; i2 < NTc*20/4; i2 += 256) dst[i2] = src[i2];
    }
    if (tid < NBMW) sbm[tid] = 0u;
    if (tid == 0) snv = d_nvalid[b];
    if (tid < NTc) {
        sconft[tid] = d_conft[b*NTc + tid];
        stcls[tid]  = d_tclsA[b*NTc + tid];
        scode[tid]  = d_codeA[b*NTc + tid];
    }
    __syncthreads();      // bitmap fully zeroed + scode/snv visible
    if (tid < NTc && tid < snv) {
        int code = scode[tid];
        atomicOr(&sbm[code >> 5], 1u << (code & 31));
    }
    __syncthreads();

    int actA = (cellA < NANCH), actB = (cellB < NANCH);

    // per-cell packed state: groups 0..3 per cell + merged corner-8 pair
    ull pxA[4], pyA[4], pxB[4], pyB[4], px8p, py8p;
    const float* cbA = out;
    const float* cbB = out;

    {
        ull big = pack2(1e30f, 1e30f);
#pragma unroll
        for (int g = 0; g < 4; ++g) { pxA[g]=big; pyA[g]=big; pxB[g]=big; pyB[g]=big; }
    }
    float px8A = 1e30f, py8A = 1e30f, px8B = 1e30f, py8B = 1e30f;
    if (actA) {
        cbA = out + ((size_t)(b*NAc + cellA/NPIX)*CH)*NPIX + (size_t)(cellA%NPIX);
        cell_setup(cbA, cellA, pxA, pyA, px8A, py8A);
    }
    if (actB) {
        cbB = out + ((size_t)(b*NAc + cellB/NPIX)*CH)*NPIX + (size_t)(cellB%NPIX);
        cell_setup(cbB, cellB, pxB, pyB, px8B, py8B);
    }
    px8p = pack2(px8A, px8B);
    py8p = pack2(py8A, py8B);

    const ull nTH2 = pack2(-TH2f, -TH2f);
    int nv = snv;
    float mA = 0.0f, mB = 0.0f;

#pragma unroll 1
    for (int t = 0; t < nv; ++t) {
        const ulonglong2* q = (const ulonglong2*)&sgt[t*20];
        ulonglong2 q0 = q[0], q1 = q[1], q2 = q[2], q3 = q[3], q4 = q[4];
        // qg.x = (-gx pair), qg.y = (-gy pair); q4 = corner8 duplicated

        ull a0 = dist2m(pxA[0], pyA[0], q0.x, q0.y, nTH2);
        ull a1 = dist2m(pxA[1], pyA[1], q1.x, q1.y, nTH2);
        ull a2 = dist2m(pxA[2], pyA[2], q2.x, q2.y, nTH2);
        ull a3 = dist2m(pxA[3], pyA[3], q3.x, q3.y, nTH2);
        ull b0 = dist2m(pxB[0], pyB[0], q0.x, q0.y, nTH2);
        ull b1 = dist2m(pxB[1], pyB[1], q1.x, q1.y, nTH2);
        ull b2 = dist2m(pxB[2], pyB[2], q2.x, q2.y, nTH2);
        ull b3 = dist2m(pxB[3], pyB[3], q3.x, q3.y, nTH2);
        ull d8 = dist2m(px8p, py8p, q4.x, q4.y, nTH2);  // (cornerA8, cornerB8)

        uint s8 = prmt_sgn(d8);
        int accA = 0, accB = 0;
        accA = dp4a_sel(prmt_sgn(a0), 0x0101u, accA);
        accA = dp4a_sel(prmt_sgn(a1), 0x0101u, accA);
        accA = dp4a_sel(prmt_sgn(a2), 0x0101u, accA);
        accA = dp4a_sel(prmt_sgn(a3), 0x0101u, accA);
        accA = dp4a_sel(s8, 0x0001u, accA);
        accB = dp4a_sel(prmt_sgn(b0), 0x0101u, accB);
        accB = dp4a_sel(prmt_sgn(b1), 0x0101u, accB);
        accB = dp4a_sel(prmt_sgn(b2), 0x0101u, accB);
        accB = dp4a_sel(prmt_sgn(b3), 0x0101u, accB);
        accB = dp4a_sel(s8, 0x0100u, accB);

        // acc = -(#corners inside). mean-conf > 0.6 (sum > 5.4) requires
        // >= 6 corners within TH (each corner conf <= 1). Exact eval rare.
        if (min(accA, accB) <= -6) {
            if (accA <= -6) mA = fmaxf(mA, exact_conf(cbA, &sgt[t*20], cellA));
            if (accB <= -6) mB = fmaxf(mB, exact_conf(cbB, &sgt[t*20], cellB));
        }
    }

    int doconf = (ep[0] > 15) ? 1 : 0;
    float contrib = 0.0f;
    if (actA) {
        int over = (mA * (1.0f/(float)Kc)) > SILf;
        int win = -1;
        if (sbm[cellA >> 5] & (1u << (cellA & 31))) {
            for (int t = nv-1; t >= 0; --t)
                if (scode[t] == cellA) { win = t; break; }
        }
        if (win >= 0 || (doconf && !over))
            contrib += cell_loss(cbA, b, win, doconf, over, sconft, stcls);
    }
    if (actB) {
        int over = (mB * (1.0f/(float)Kc)) > SILf;
        int win = -1;
        if (sbm[cellB >> 5] & (1u << (cellB & 31))) {
            for (int t = nv-1; t >= 0; --t)
                if (scode[t] == cellB) { win = t; break; }
        }
        if (win >= 0 || (doconf && !over))
            contrib += cell_loss(cbB, b, win, doconf, over, sconft, stcls);
    }

    // warp-shuffle reduction + one atomic per block
#pragma unroll
    for (int off = 16; off > 0; off >>= 1)
        contrib += __shfl_down_sync(0xFFFFFFFFu, contrib, off);
    int lane = tid & 31, wid = tid >> 5;
    if (lane == 0) wred[wid] = contrib;
    __syncthreads();
    if (tid < 8) {
        float v = wred[tid];
#pragma unroll
        for (int off = 4; off > 0; off >>= 1)
            v += __shfl_down_sync(0xFFu, v, off);
        if (tid == 0) atomicAdd(loss, v);
    }
}

extern "C" void kernel_launch(void* const* d_in, const int* in_sizes, int n_in,
                              void* d_out, int out_size)
{
    const float* out = (const float*)d_in[0];
    const float* tgt = (const float*)d_in[1];
    const int*   ep  = (const int*)d_in[2];
    float* loss = (float*)d_out;

    region_prep<<<NBc, 64>>>(out, tgt, loss);
    dim3 g((NANCH + 511)/512, NBc);
    region_main<<<g, 256>>>(out, ep, loss);
}

// round 9
// speedup vs baseline: 1.0636x; 1.0039x over previous
#include <cuda_runtime.h>

// Problem constants
#define Kc    9
#define NCc   13
#define NAc   5
#define NBc   128
#define NHc   26
#define NWc   26
#define NTc   50
#define Lc    21          // 2K+3
#define NPIX  (NHc*NWc)   // 676
#define NANCH (NAc*NHc*NWc) // 3380
#define CH    (2*Kc+1+NCc) // 32
#define NBMW  106          // ceil(3380/32)

#define THf     80.0f
#define TH2f    6400.0f
#define SILf    0.6f
#define OBJf    5.0f
// 1/(exp(2)-1)
#define INVC0   0.15651764274966574f

#define SXc (640.0f/26.0f)
#define SYc (480.0f/26.0f)

typedef unsigned long long ull;
typedef unsigned int uint;

// Scratch (device globals — no allocation allowed)
// Per (b,t): 20 floats = 5 float4; group g in 0..3 (corner pair 2g,2g+1):
//   [g*4+0]=-gx_{2g}  [g*4+1]=-gx_{2g+1}  [g*4+2]=-gy_{2g}  [g*4+3]=-gy_{2g+1}
// group 4 = corner 8 DUPLICATED: [16]=-gx8 [17]=-gx8 [18]=-gy8 [19]=-gy8
__device__ __align__(16) float d_gtn[NBc*NTc*20];
__device__ float d_txv[NBc*NTc*Kc];
__device__ float d_tyv[NBc*NTc*Kc];
__device__ float d_conft[NBc*NTc];
__device__ float d_tclsA[NBc*NTc];
__device__ int   d_codeA[NBc*NTc];
__device__ int   d_nvalid[NBc];

__constant__ float c_anch[10] = {1.482f,2.2412f,2.0501f,3.1265f,2.3946f,
                                 4.6891f,3.1018f,3.991f,3.4879f,5.8851f};

__device__ __forceinline__ float sigmoidf_(float x) { return 1.0f/(1.0f+expf(-x)); }

__device__ __forceinline__ ull pack2(float lo, float hi) {
    ull r;
    asm("mov.b64 %0, {%1, %2};" : "=l"(r) : "f"(lo), "f"(hi));
    return r;
}
__device__ __forceinline__ ull fma2_(ull a, ull b, ull c) {
    ull d;
    asm("fma.rn.f32x2 %0, %1, %2, %3;" : "=l"(d) : "l"(a), "l"(b), "l"(c));
    return d;
}
__device__ __forceinline__ ull add2_(ull a, ull b) {
    ull d;
    asm("add.rn.f32x2 %0, %1, %2;" : "=l"(d) : "l"(a), "l"(b));
    return d;
}
// d^2 - TH^2 for a corner pair (direct form)
__device__ __forceinline__ ull dist2m(ull px, ull py, ull ngx, ull ngy, ull nTH2) {
    ull dx = add2_(px, ngx);
    ull dy = add2_(py, ngy);
    return fma2_(dx, dx, fma2_(dy, dy, nTH2));
}
// sign bytes of the two packed floats in d -> bytes0,1 as 0xFF/0x00
__device__ __forceinline__ uint prmt_sgn(ull d) {
    uint lo = (uint)d, hi = (uint)(d >> 32), r;
    asm("prmt.b32 %0, %1, %2, 0x000000FB;" : "=r"(r) : "r"(lo), "r"(hi));
    return r;
}
// acc += dot(sign bytes, sel) (sel selects which bytes count, -1 per inside)
__device__ __forceinline__ int dp4a_sel(uint s, uint sel, int acc) {
    int r;
    asm("dp4a.s32.s32 %0, %1, %2, %3;" : "=r"(r) : "r"(s), "r"(sel), "r"(acc));
    return r;
}

// One block per batch; thread t handles target t. Also zeroes the loss scalar.
__global__ void region_prep(const float* __restrict__ out,
                            const float* __restrict__ tgt,
                            float* __restrict__ loss)
{
    int b = blockIdx.x;
    int t = threadIdx.x;
    if (b == 0 && t == 0) loss[0] = 0.0f;

    __shared__ int sflag[NTc];
    if (t < NTc)
        sflag[t] = (tgt[(size_t)b*NTc*Lc + (size_t)t*Lc + 1] != 0.0f) ? 1 : 0;
    __syncthreads();
    if (t == 0) {
        int nv = NTc;
        for (int q = 0; q < NTc; ++q) if (!sflag[q]) { nv = q; break; }
        d_nvalid[b] = nv;
    }
    if (t >= NTc) return;

    const float* row = tgt + (size_t)b*NTc*Lc + (size_t)t*Lc;
    float gxr[Kc], gyr[Kc];
#pragma unroll
    for (int k = 0; k < Kc; ++k) { gxr[k] = row[1+2*k]; gyr[k] = row[2+2*k]; }

    int gi0 = (int)floorf(gxr[0]*(float)NWc);
    int gj0 = (int)floorf(gyr[0]*(float)NHc);
    gi0 = min(max(gi0, 0), NWc-1);
    gj0 = min(max(gj0, 0), NHc-1);

    int idx = b*NTc + t;

    float gpx[Kc], gpy[Kc];
#pragma unroll
    for (int k = 0; k < Kc; ++k) {
        gpx[k] = gxr[k]*640.0f;
        gpy[k] = gyr[k]*480.0f;
        d_txv[idx*Kc+k] = gxr[k]*(float)NWc - (float)gi0;
        d_tyv[idx*Kc+k] = gyr[k]*(float)NHc - (float)gj0;
    }
    float* gt = &d_gtn[idx*20];
#pragma unroll
    for (int g = 0; g < 4; ++g) {
        gt[g*4+0] = -gpx[2*g];  gt[g*4+1] = -gpx[2*g+1];
        gt[g*4+2] = -gpy[2*g];  gt[g*4+3] = -gpy[2*g+1];
    }
    gt[16] = -gpx[8]; gt[17] = -gpx[8]; gt[18] = -gpy[8]; gt[19] = -gpy[8];

    // best anchor by IoU on (gw, gh); first max wins (strict >)
    float gw = row[Lc-2]*(float)NWc;
    float gh = row[Lc-1]*(float)NHc;
    float best = -1.0f; int bn = 0;
#pragma unroll
    for (int a = 0; a < NAc; ++a) {
        float aw = c_anch[2*a], ah = c_anch[2*a+1];
        float mw = fminf(aw, gw), mh = fminf(ah, gh);
        float inter = mw*mh;
        float iou = inter / (aw*ah + gw*gh - inter);
        if (iou > best) { best = iou; bn = a; }
    }
    d_codeA[idx] = bn*NPIX + gj0*NWc + gi0;
    d_tclsA[idx] = row[0];

    // conf_t: gather pred box from batch (b-1 mod NB), anchor NA-1, cell (gj0, gi0)
    int bp = (b + NBc - 1) % NBc;
    const float* cb = out + ((size_t)(bp*NAc + (NAc-1))*CH)*NPIX
                          + (size_t)(gj0*NWc + gi0);
    float acc = 0.0f;
#pragma unroll
    for (int k = 0; k < Kc; ++k) {
        float xv = cb[(2*k)*NPIX];
        float yv = cb[(2*k+1)*NPIX];
        if (k == 0) { xv = sigmoidf_(xv); yv = sigmoidf_(yv); }
        float px = (xv + (float)gi0) * (1.0f/(float)NWc);
        float py = (yv + (float)gj0) * (1.0f/(float)NHc);
        float dx = (px - gxr[k]) * 640.0f;
        float dy = (py - gyr[k]) * 480.0f;
        float d2 = fmaf(dx, dx, dy*dy);
        if (d2 < TH2f) {
            float d = sqrtf(d2);
            acc += (expf(2.0f - d*0.025f) - 1.0f) * INVC0;
        }
    }
    d_conft[idx] = acc * (1.0f/(float)Kc);
}

// COLD: full rescan of all targets for one cell with exact evaluation.
// Runs only for the rare lanes whose branchless screen flagged a possible hit.
// Decision logic identical to the packed screen: count corners with
// d^2 < TH^2; if >= 6, evaluate exact corner-conf sum and take the max.
__device__ __noinline__ float rescan_cell(const float* __restrict__ cb,
                                          const float* __restrict__ sgt,
                                          int cell, int nv)
{
    int a = cell / NPIX, pos = cell - a*NPIX;
    int jj = pos / NWc, ii = pos - jj*NWc;
    float fx = (float)ii * SXc, fy = (float)jj * SYc;
    float pxs[Kc], pys[Kc];
#pragma unroll
    for (int k = 0; k < Kc; ++k) {
        float xv = cb[(2*k)*NPIX];
        float yv = cb[(2*k+1)*NPIX];
        if (k == 0) { xv = sigmoidf_(xv); yv = sigmoidf_(yv); }
        pxs[k] = fmaf(xv, SXc, fx);
        pys[k] = fmaf(yv, SYc, fy);
    }
    float m = 0.0f;
    for (int t = 0; t < nv; ++t) {
        const float* tp = &sgt[t*20];
        int cnt = 0;
        float d2s[Kc];
#pragma unroll
        for (int k = 0; k < Kc; ++k) {
            float ngx = tp[(k>>1)*4 + (k&1)];
            float ngy = tp[(k>>1)*4 + 2 + (k&1)];
            float dx = pxs[k] + ngx;
            float dy = pys[k] + ngy;
            float dd = fmaf(dx, dx, fmaf(dy, dy, -TH2f));
            d2s[k] = dd;
            cnt += (__float_as_uint(dd) >> 31);
        }
        if (cnt >= 6) {
            float acc = 0.0f;
#pragma unroll
            for (int k = 0; k < Kc; ++k) {
                if (d2s[k] < 0.0f) {
                    float d = sqrtf(d2s[k] + TH2f);
                    acc += (expf(2.0f - d*0.025f) - 1.0f) * INVC0;
                }
            }
            m = fmaxf(m, acc);
        }
    }
    return m;
}

// rare per-object-cell / noobj epilogue
__device__ __noinline__ float cell_loss(const float* __restrict__ cb,
                                        int b, int win, int doconf, int over_sil,
                                        const float* __restrict__ sconft,
                                        const float* __restrict__ stcls)
{
    float contrib = 0.0f;
    if (win >= 0) {
        const float* txp = &d_txv[(b*NTc + win)*Kc];
        const float* typ = &d_tyv[(b*NTc + win)*Kc];
        float cl = 0.0f;
#pragma unroll
        for (int k = 0; k < Kc; ++k) {
            float xv = cb[(2*k)*NPIX];
            float yv = cb[(2*k+1)*NPIX];
            if (k == 0) { xv = sigmoidf_(xv); yv = sigmoidf_(yv); }
            float exd = xv - txp[k];
            float eyd = yv - typ[k];
            cl += exd*exd + eyd*eyd;
        }
        contrib = 0.5f*cl;

        float lg[NCc];
        float mx = -1e30f;
#pragma unroll
        for (int c = 0; c < NCc; ++c) {
            lg[c] = cb[(2*Kc+1+c)*NPIX];
            mx = fmaxf(mx, lg[c]);
        }
        float se = 0.0f;
#pragma unroll
        for (int c = 0; c < NCc; ++c) se += expf(lg[c]-mx);
        int lab = (int)stcls[win];
        lab = min(max(lab, 0), NCc-1);
        contrib += (mx + logf(se)) - lg[lab];

        if (doconf) {
            float conf = sigmoidf_(cb[(2*Kc)*NPIX]);
            float dc = conf - sconft[win];
            contrib += 0.5f*OBJf*dc*dc;
        }
    } else {
        if (doconf && !over_sil) {
            float conf = sigmoidf_(cb[(2*Kc)*NPIX]);
            contrib += 0.5f*conf*conf;
        }
    }
    return contrib;
}

// fill packed corner pairs (groups 0..3) + scalar corner 8 for one cell
__device__ __forceinline__ void cell_setup(const float* __restrict__ cb,
                                           int cell, ull* px, ull* py,
                                           float& px8, float& py8)
{
    int a = cell / NPIX, pos = cell - a*NPIX;
    int jj = pos / NWc, ii = pos - jj*NWc;
    float fx = (float)ii * SXc, fy = (float)jj * SYc;
    float pxs[Kc], pys[Kc];
#pragma unroll
    for (int k = 0; k < Kc; ++k) {
        float xv = cb[(2*k)*NPIX];
        float yv = cb[(2*k+1)*NPIX];
        if (k == 0) { xv = sigmoidf_(xv); yv = sigmoidf_(yv); }
        pxs[k] = fmaf(xv, SXc, fx);
        pys[k] = fmaf(yv, SYc, fy);
    }
#pragma unroll
    for (int g = 0; g < 4; ++g) {
        px[g] = pack2(pxs[2*g], pxs[2*g+1]);
        py[g] = pack2(pys[2*g], pys[2*g+1]);
    }
    px8 = pxs[8]; py8 = pys[8];
}

// grid: (ceil(NANCH/512), NB) ; each thread handles 2 cells (tid, tid+256)
__global__ __launch_bounds__(256, 4)
void region_main(const float* __restrict__ out,
                 const int*   __restrict__ ep,
                 float* __restrict__ loss)
{
    int b   = blockIdx.y;
    int tid = threadIdx.x;
    int cellA = blockIdx.x*512 + tid;
    int cellB = cellA + 256;

    __shared__ __align__(16) float sgt[NTc*20];
    __shared__ float sconft[NTc], stcls[NTc];
    __shared__ int   scode[NTc];
    __shared__ uint  sbm[NBMW];
    __shared__ float wred[8];
    __shared__ int   snv;

    {
        const float4* src = (const float4*)&d_gtn[b*NTc*20];
        float4* dst = (float4*)sgt;
        for (int i2 = tid; i2 < NTc*20/4; i2 += 256) dst[i2] = src[i2];
    }
    if (tid < NBMW) sbm[tid] = 0u;
    if (tid == 0) snv = d_nvalid[b];
    if (tid < NTc) {
        sconft[tid] = d_conft[b*NTc + tid];
        stcls[tid]  = d_tclsA[b*NTc + tid];
        scode[tid]  = d_codeA[b*NTc + tid];
    }
    __syncthreads();      // bitmap fully zeroed + scode/snv visible
    if (tid < NTc && tid < snv) {
        int code = scode[tid];
        atomicOr(&sbm[code >> 5], 1u << (code & 31));
    }
    __syncthreads();

    int actA = (cellA < NANCH), actB = (cellB < NANCH);

    // per-cell packed state: groups 0..3 per cell + merged corner-8 pair
    ull pxA[4], pyA[4], pxB[4], pyB[4], px8p, py8p;
    const float* cbA = out;
    const float* cbB = out;

    {
        ull big = pack2(1e30f, 1e30f);
#pragma unroll
        for (int g = 0; g < 4; ++g) { pxA[g]=big; pyA[g]=big; pxB[g]=big; pyB[g]=big; }
    }
    float px8A = 1e30f, py8A = 1e30f, px8B = 1e30f, py8B = 1e30f;
    if (actA) {
        cbA = out + ((size_t)(b*NAc + cellA/NPIX)*CH)*NPIX + (size_t)(cellA%NPIX);
        cell_setup(cbA, cellA, pxA, pyA, px8A, py8A);
    }
    if (actB) {
        cbB = out + ((size_t)(b*NAc + cellB/NPIX)*CH)*NPIX + (size_t)(cellB%NPIX);
        cell_setup(cbB, cellB, pxB, pyB, px8B, py8B);
    }
    px8p = pack2(px8A, px8B);
    py8p = pack2(py8A, py8B);

    const ull nTH2 = pack2(-TH2f, -TH2f);
    int nv = snv;
    int maccA = 0, maccB = 0;

    // BRANCHLESS hot loop: track min count per cell; no data-dependent branch.
#pragma unroll 1
    for (int t = 0; t < nv; ++t) {
        const ulonglong2* q = (const ulonglong2*)&sgt[t*20];
        ulonglong2 q0 = q[0], q1 = q[1], q2 = q[2], q3 = q[3], q4 = q[4];
        // qg.x = (-gx pair), qg.y = (-gy pair); q4 = corner8 duplicated

        ull a0 = dist2m(pxA[0], pyA[0], q0.x, q0.y, nTH2);
        ull a1 = dist2m(pxA[1], pyA[1], q1.x, q1.y, nTH2);
        ull a2 = dist2m(pxA[2], pyA[2], q2.x, q2.y, nTH2);
        ull a3 = dist2m(pxA[3], pyA[3], q3.x, q3.y, nTH2);
        ull b0 = dist2m(pxB[0], pyB[0], q0.x, q0.y, nTH2);
        ull b1 = dist2m(pxB[1], pyB[1], q1.x, q1.y, nTH2);
        ull b2 = dist2m(pxB[2], pyB[2], q2.x, q2.y, nTH2);
        ull b3 = dist2m(pxB[3], pyB[3], q3.x, q3.y, nTH2);
        ull d8 = dist2m(px8p, py8p, q4.x, q4.y, nTH2);  // (cornerA8, cornerB8)

        uint s8 = prmt_sgn(d8);
        // two shallow chains per cell, then combine (shorter critical path)
        int aA0 = dp4a_sel(prmt_sgn(a0), 0x0101u,
                  dp4a_sel(prmt_sgn(a1), 0x0101u, 0));
        int aA1 = dp4a_sel(prmt_sgn(a2), 0x0101u,
                  dp4a_sel(prmt_sgn(a3), 0x0101u,
                  dp4a_sel(s8, 0x0001u, 0)));
        int aB0 = dp4a_sel(prmt_sgn(b0), 0x0101u,
                  dp4a_sel(prmt_sgn(b1), 0x0101u, 0));
        int aB1 = dp4a_sel(prmt_sgn(b2), 0x0101u,
                  dp4a_sel(prmt_sgn(b3), 0x0101u,
                  dp4a_sel(s8, 0x0100u, 0)));

        maccA = min(maccA, aA0 + aA1);
        maccB = min(maccB, aB0 + aB1);
    }

    // acc = -(#corners inside). mean-conf > 0.6 (sum > 5.4) requires >= 6
    // corners within TH (each corner conf <= 1). Cold rescan only if any
    // target could pass (per-lane rare).
    float mA = 0.0f, mB = 0.0f;
    if (maccA <= -6) mA = rescan_cell(cbA, sgt, cellA, nv);
    if (maccB <= -6) mB = rescan_cell(cbB, sgt, cellB, nv);

    int doconf = (ep[0] > 15) ? 1 : 0;
    float contrib = 0.0f;
    if (actA) {
        int over = (mA * (1.0f/(float)Kc)) > SILf;
        int win = -1;
        if (sbm[cellA >> 5] & (1u << (cellA & 31))) {
            for (int t = nv-1; t >= 0; --t)
                if (scode[t] == cellA) { win = t; break; }
        }
        if (win >= 0 || (doconf && !over))
            contrib += cell_loss(cbA, b, win, doconf, over, sconft, stcls);
    }
    if (actB) {
        int over = (mB * (1.0f/(float)Kc)) > SILf;
        int win = -1;
        if (sbm[cellB >> 5] & (1u << (cellB & 31))) {
            for (int t = nv-1; t >= 0; --t)
                if (scode[t] == cellB) { win = t; break; }
        }
        if (win >= 0 || (doconf && !over))
            contrib += cell_loss(cbB, b, win, doconf, over, sconft, stcls);
    }

    // warp-shuffle reduction + one atomic per block
#pragma unroll
    for (int off = 16; off > 0; off >>= 1)
        contrib += __shfl_down_sync(0xFFFFFFFFu, contrib, off);
    int lane = tid & 31, wid = tid >> 5;
    if (lane == 0) wred[wid] = contrib;
    __syncthreads();
    if (tid < 8) {
        float v = wred[tid];
#pragma unroll
        for (int off = 4; off > 0; off >>= 1)
            v += __shfl_down_sync(0xFFu, v, off);
        if (tid == 0) atomicAdd(loss, v);
    }
}

extern "C" void kernel_launch(void* const* d_in, const int* in_sizes, int n_in,
                              void* d_out, int out_size)
{
    const float* out = (const float*)d_in[0];
    const float* tgt = (const float*)d_in[1];
    const int*   ep  = (const int*)d_in[2];
    float* loss = (float*)d_out;

    region_prep<<<NBc, 64>>>(out, tgt, loss);
    dim3 g((NANCH + 511)/512, NBc);
    region_main<<<g, 256>>>(out, ep, loss);
}